// round 1
// baseline (speedup 1.0000x reference)
#include <cuda_runtime.h>

#define NB 8
#define NS 1024
#define ND 256
#define NH 8
#define NBH 64          // B*H
#define HD 2048         // H*D

// Scratch (static device memory — allocation-free per harness rules)
__device__ float g_Q[NBH * NS * ND];           // 64 MB
__device__ float g_K[NBH * NS * ND];           // 64 MB
__device__ float g_V[NBH * NS * ND];           // 64 MB
__device__ float g_P[67108864];                // NBH*NS*NS = 256 MB
__device__ float g_O[NBH * NS * ND];           // 64 MB

// ---------------------------------------------------------------------------
// Kernel 1: fused QKV projection.
// For each (b,h): Q/K/V[s,e] = sum_d X[b,s,e..] * W{q,k,v}[h,e,d] + b{q,k,v}[h,e]
// NT GEMM (both operands K-contiguous). X tile loaded once, used by 3 accums.
// ---------------------------------------------------------------------------
__global__ __launch_bounds__(256) void qkv_kernel(
    const float* __restrict__ x,
    const float* __restrict__ Wq, const float* __restrict__ Wk,
    const float* __restrict__ Wv,
    const float* __restrict__ bq, const float* __restrict__ bk,
    const float* __restrict__ bv)
{
    int bh = blockIdx.z;
    int b = bh >> 3, h = bh & 7;
    int m0 = blockIdx.x * 64;       // s tile
    int n0 = blockIdx.y * 64;       // e tile

    const float* A  = x  + b * NS * ND;
    const float* W0 = Wq + h * ND * ND;
    const float* W1 = Wk + h * ND * ND;
    const float* W2 = Wv + h * ND * ND;

    __shared__ float As[16][64];
    __shared__ float Bs[3][16][64];

    int t  = threadIdx.x;
    int lm = t >> 2, lk = (t & 3) << 2;   // tile-load coords
    int tx = t & 15, ty = t >> 4;         // compute coords

    float acc[3][4][4];
    #pragma unroll
    for (int q = 0; q < 3; q++)
        #pragma unroll
        for (int i = 0; i < 4; i++)
            #pragma unroll
            for (int j = 0; j < 4; j++) acc[q][i][j] = 0.f;

    for (int k0 = 0; k0 < ND; k0 += 16) {
        float4 av = *(const float4*)(A  + (m0 + lm) * ND + k0 + lk);
        float4 w0 = *(const float4*)(W0 + (n0 + lm) * ND + k0 + lk);
        float4 w1 = *(const float4*)(W1 + (n0 + lm) * ND + k0 + lk);
        float4 w2 = *(const float4*)(W2 + (n0 + lm) * ND + k0 + lk);
        As[lk + 0][lm] = av.x; As[lk + 1][lm] = av.y;
        As[lk + 2][lm] = av.z; As[lk + 3][lm] = av.w;
        Bs[0][lk + 0][lm] = w0.x; Bs[0][lk + 1][lm] = w0.y;
        Bs[0][lk + 2][lm] = w0.z; Bs[0][lk + 3][lm] = w0.w;
        Bs[1][lk + 0][lm] = w1.x; Bs[1][lk + 1][lm] = w1.y;
        Bs[1][lk + 2][lm] = w1.z; Bs[1][lk + 3][lm] = w1.w;
        Bs[2][lk + 0][lm] = w2.x; Bs[2][lk + 1][lm] = w2.y;
        Bs[2][lk + 2][lm] = w2.z; Bs[2][lk + 3][lm] = w2.w;
        __syncthreads();

        #pragma unroll
        for (int kk = 0; kk < 16; ++kk) {
            float4 a  = *(const float4*)&As[kk][ty << 2];
            float4 b0 = *(const float4*)&Bs[0][kk][tx << 2];
            float4 b1 = *(const float4*)&Bs[1][kk][tx << 2];
            float4 b2 = *(const float4*)&Bs[2][kk][tx << 2];
            float aa[4] = {a.x, a.y, a.z, a.w};
            float v0[4] = {b0.x, b0.y, b0.z, b0.w};
            float v1[4] = {b1.x, b1.y, b1.z, b1.w};
            float v2[4] = {b2.x, b2.y, b2.z, b2.w};
            #pragma unroll
            for (int i = 0; i < 4; i++)
                #pragma unroll
                for (int j = 0; j < 4; j++) {
                    acc[0][i][j] = fmaf(aa[i], v0[j], acc[0][i][j]);
                    acc[1][i][j] = fmaf(aa[i], v1[j], acc[1][i][j]);
                    acc[2][i][j] = fmaf(aa[i], v2[j], acc[2][i][j]);
                }
        }
        __syncthreads();
    }

    float* outs[3] = {g_Q, g_K, g_V};
    const float* biases[3] = {bq, bk, bv};
    #pragma unroll
    for (int q = 0; q < 3; q++) {
        float4 bv4 = *(const float4*)(biases[q] + h * ND + n0 + (tx << 2));
        float* Cp = outs[q] + (bh * NS + m0 + (ty << 2)) * ND + n0 + (tx << 2);
        #pragma unroll
        for (int i = 0; i < 4; i++) {
            float4 o;
            o.x = acc[q][i][0] + bv4.x;
            o.y = acc[q][i][1] + bv4.y;
            o.z = acc[q][i][2] + bv4.z;
            o.w = acc[q][i][3] + bv4.w;
            *(float4*)(Cp + i * ND) = o;
        }
    }
}

// ---------------------------------------------------------------------------
// Kernel 2: scores = (Q @ K^T) / 16   per (b,h).  NT GEMM M=N=1024, K=256.
// ---------------------------------------------------------------------------
__global__ __launch_bounds__(256) void scores_kernel()
{
    int bh = blockIdx.z;
    int m0 = blockIdx.x * 64, n0 = blockIdx.y * 64;
    const float* A  = g_Q + bh * NS * ND;
    const float* Bm = g_K + bh * NS * ND;
    float* C = g_P + (size_t)bh * NS * NS;

    __shared__ float As[16][64];
    __shared__ float Bs[16][64];

    int t  = threadIdx.x;
    int lm = t >> 2, lk = (t & 3) << 2;
    int tx = t & 15, ty = t >> 4;

    float acc[4][4];
    #pragma unroll
    for (int i = 0; i < 4; i++)
        #pragma unroll
        for (int j = 0; j < 4; j++) acc[i][j] = 0.f;

    for (int k0 = 0; k0 < ND; k0 += 16) {
        float4 av = *(const float4*)(A  + (m0 + lm) * ND + k0 + lk);
        float4 bv = *(const float4*)(Bm + (n0 + lm) * ND + k0 + lk);
        As[lk + 0][lm] = av.x; As[lk + 1][lm] = av.y;
        As[lk + 2][lm] = av.z; As[lk + 3][lm] = av.w;
        Bs[lk + 0][lm] = bv.x; Bs[lk + 1][lm] = bv.y;
        Bs[lk + 2][lm] = bv.z; Bs[lk + 3][lm] = bv.w;
        __syncthreads();

        #pragma unroll
        for (int kk = 0; kk < 16; ++kk) {
            float4 a = *(const float4*)&As[kk][ty << 2];
            float4 b = *(const float4*)&Bs[kk][tx << 2];
            float aa[4] = {a.x, a.y, a.z, a.w};
            float bb[4] = {b.x, b.y, b.z, b.w};
            #pragma unroll
            for (int i = 0; i < 4; i++)
                #pragma unroll
                for (int j = 0; j < 4; j++)
                    acc[i][j] = fmaf(aa[i], bb[j], acc[i][j]);
        }
        __syncthreads();
    }

    const float alpha = 0.0625f;   // 1/sqrt(256)
    #pragma unroll
    for (int i = 0; i < 4; i++) {
        float4 o;
        o.x = acc[i][0] * alpha; o.y = acc[i][1] * alpha;
        o.z = acc[i][2] * alpha; o.w = acc[i][3] * alpha;
        *(float4*)(C + (size_t)(m0 + (ty << 2) + i) * NS + n0 + (tx << 2)) = o;
    }
}

// ---------------------------------------------------------------------------
// Kernel 3: row softmax over keys.  One block (256 thr) per row of 1024.
// ---------------------------------------------------------------------------
__global__ __launch_bounds__(256) void softmax_kernel()
{
    float* p = g_P + (size_t)blockIdx.x * NS;
    int t = threadIdx.x;

    float4 v = *(float4*)(p + (t << 2));
    __shared__ float sm[8], ss[8];

    float m = fmaxf(fmaxf(v.x, v.y), fmaxf(v.z, v.w));
    #pragma unroll
    for (int o = 16; o > 0; o >>= 1) m = fmaxf(m, __shfl_xor_sync(0xffffffffu, m, o));
    if ((t & 31) == 0) sm[t >> 5] = m;
    __syncthreads();
    if (t < 32) {
        float mm = (t < 8) ? sm[t] : -3.0e38f;
        #pragma unroll
        for (int o = 4; o > 0; o >>= 1) mm = fmaxf(mm, __shfl_xor_sync(0xffffffffu, mm, o));
        if (t == 0) sm[0] = mm;
    }
    __syncthreads();
    m = sm[0];

    v.x = __expf(v.x - m); v.y = __expf(v.y - m);
    v.z = __expf(v.z - m); v.w = __expf(v.w - m);
    float s = v.x + v.y + v.z + v.w;
    #pragma unroll
    for (int o = 16; o > 0; o >>= 1) s += __shfl_xor_sync(0xffffffffu, s, o);
    if ((t & 31) == 0) ss[t >> 5] = s;
    __syncthreads();
    if (t < 32) {
        float sv = (t < 8) ? ss[t] : 0.f;
        #pragma unroll
        for (int o = 4; o > 0; o >>= 1) sv += __shfl_xor_sync(0xffffffffu, sv, o);
        if (t == 0) ss[0] = sv;
    }
    __syncthreads();
    float inv = 1.0f / ss[0];
    v.x *= inv; v.y *= inv; v.z *= inv; v.w *= inv;
    *(float4*)(p + (t << 2)) = v;
}

// ---------------------------------------------------------------------------
// Kernel 4: O = P @ V  per (b,h).  NN GEMM  M=1024, N=256, K=1024.
// ---------------------------------------------------------------------------
__global__ __launch_bounds__(256) void av_kernel()
{
    int bh = blockIdx.z;
    int m0 = blockIdx.x * 64, n0 = blockIdx.y * 64;
    const float* A  = g_P + (size_t)bh * NS * NS;   // [s, t], ld=1024
    const float* Bm = g_V + bh * NS * ND;           // [t, e], ld=256
    float* C = g_O + bh * NS * ND;

    __shared__ float As[16][64];
    __shared__ float Bs[16][64];

    int t   = threadIdx.x;
    int lm  = t >> 2,  lk  = (t & 3) << 2;     // A-tile
    int lk2 = t >> 4,  ln  = (t & 15) << 2;    // B-tile (NN)
    int tx  = t & 15,  ty  = t >> 4;

    float acc[4][4];
    #pragma unroll
    for (int i = 0; i < 4; i++)
        #pragma unroll
        for (int j = 0; j < 4; j++) acc[i][j] = 0.f;

    for (int k0 = 0; k0 < NS; k0 += 16) {
        float4 av = *(const float4*)(A + (size_t)(m0 + lm) * NS + k0 + lk);
        As[lk + 0][lm] = av.x; As[lk + 1][lm] = av.y;
        As[lk + 2][lm] = av.z; As[lk + 3][lm] = av.w;
        float4 bv = *(const float4*)(Bm + (k0 + lk2) * ND + n0 + ln);
        *(float4*)&Bs[lk2][ln] = bv;
        __syncthreads();

        #pragma unroll
        for (int kk = 0; kk < 16; ++kk) {
            float4 a = *(const float4*)&As[kk][ty << 2];
            float4 b = *(const float4*)&Bs[kk][tx << 2];
            float aa[4] = {a.x, a.y, a.z, a.w};
            float bb[4] = {b.x, b.y, b.z, b.w};
            #pragma unroll
            for (int i = 0; i < 4; i++)
                #pragma unroll
                for (int j = 0; j < 4; j++)
                    acc[i][j] = fmaf(aa[i], bb[j], acc[i][j]);
        }
        __syncthreads();
    }

    #pragma unroll
    for (int i = 0; i < 4; i++) {
        float4 o;
        o.x = acc[i][0]; o.y = acc[i][1]; o.z = acc[i][2]; o.w = acc[i][3];
        *(float4*)(C + (m0 + (ty << 2) + i) * ND + n0 + (tx << 2)) = o;
    }
}

// ---------------------------------------------------------------------------
// Kernel 5: out[b,s,:] = concat_h(O) @ Wp^T.  NT GEMM M=8192, N=256, K=2048.
// Concat folded into A-tile gather indexing.
// ---------------------------------------------------------------------------
__global__ __launch_bounds__(256) void proj_kernel(
    const float* __restrict__ Wp, float* __restrict__ out)
{
    int m0 = blockIdx.x * 64;    // over B*S = 8192
    int n0 = blockIdx.y * 64;    // over D = 256

    __shared__ float As[16][64];
    __shared__ float Bs[16][64];

    int t  = threadIdx.x;
    int lm = t >> 2, lk = (t & 3) << 2;
    int tx = t & 15, ty = t >> 4;

    int m = m0 + lm;
    int b = m >> 10, s = m & 1023;

    float acc[4][4];
    #pragma unroll
    for (int i = 0; i < 4; i++)
        #pragma unroll
        for (int j = 0; j < 4; j++) acc[i][j] = 0.f;

    for (int k0 = 0; k0 < HD; k0 += 16) {
        int k = k0 + lk;
        int h = k >> 8, e = k & 255;
        float4 av = *(const float4*)(g_O + ((b * NH + h) * NS + s) * ND + e);
        float4 bv = *(const float4*)(Wp + (n0 + lm) * HD + k0 + lk);
        As[lk + 0][lm] = av.x; As[lk + 1][lm] = av.y;
        As[lk + 2][lm] = av.z; As[lk + 3][lm] = av.w;
        Bs[lk + 0][lm] = bv.x; Bs[lk + 1][lm] = bv.y;
        Bs[lk + 2][lm] = bv.z; Bs[lk + 3][lm] = bv.w;
        __syncthreads();

        #pragma unroll
        for (int kk = 0; kk < 16; ++kk) {
            float4 a = *(const float4*)&As[kk][ty << 2];
            float4 bq = *(const float4*)&Bs[kk][tx << 2];
            float aa[4] = {a.x, a.y, a.z, a.w};
            float bb[4] = {bq.x, bq.y, bq.z, bq.w};
            #pragma unroll
            for (int i = 0; i < 4; i++)
                #pragma unroll
                for (int j = 0; j < 4; j++)
                    acc[i][j] = fmaf(aa[i], bb[j], acc[i][j]);
        }
        __syncthreads();
    }

    #pragma unroll
    for (int i = 0; i < 4; i++) {
        float4 o;
        o.x = acc[i][0]; o.y = acc[i][1]; o.z = acc[i][2]; o.w = acc[i][3];
        *(float4*)(out + (m0 + (ty << 2) + i) * ND + n0 + (tx << 2)) = o;
    }
}

// ---------------------------------------------------------------------------
extern "C" void kernel_launch(void* const* d_in, const int* in_sizes, int n_in,
                              void* d_out, int out_size)
{
    const float* x  = (const float*)d_in[0];
    const float* Wq = (const float*)d_in[1];
    const float* Wk = (const float*)d_in[2];
    const float* Wv = (const float*)d_in[3];
    const float* bq = (const float*)d_in[4];
    const float* bk = (const float*)d_in[5];
    const float* bv = (const float*)d_in[6];
    const float* Wp = (const float*)d_in[7];
    float* out = (float*)d_out;

    dim3 g1(16, 4, 64);
    qkv_kernel<<<g1, 256>>>(x, Wq, Wk, Wv, bq, bk, bv);

    dim3 g2(16, 16, 64);
    scores_kernel<<<g2, 256>>>();

    softmax_kernel<<<65536, 256>>>();

    dim3 g3(16, 4, 64);
    av_kernel<<<g3, 256>>>();

    dim3 g4(128, 4, 1);
    proj_kernel<<<g4, 256>>>(Wp, out);
}

// round 3
// speedup vs baseline: 2.3689x; 2.3689x over previous
#include <cuda_runtime.h>
#include <cuda_bf16.h>
#include <cstdint>

#define NS 1024
#define ND 256
#define NH 8
#define HD 2048

// ---------------- scratch (static device memory; no allocs) ----------------
__device__ float g_P[67108864];                                   // 256 MB fp32 scores
__device__ __nv_bfloat16 g_Xhi[2097152],  g_Xlo[2097152];
__device__ __nv_bfloat16 g_Wqhi[524288],  g_Wqlo[524288];
__device__ __nv_bfloat16 g_Wkhi[524288],  g_Wklo[524288];
__device__ __nv_bfloat16 g_Wvhi[524288],  g_Wvlo[524288];
__device__ __nv_bfloat16 g_Wphi[524288],  g_Wplo[524288];
__device__ __nv_bfloat16 g_Qhi[16777216], g_Qlo[16777216];
__device__ __nv_bfloat16 g_Khi[16777216], g_Klo[16777216];
__device__ __nv_bfloat16 g_Vhi[16777216], g_Vlo[16777216];
__device__ __nv_bfloat16 g_Vthi[16777216], g_Vtlo[16777216];     // V transposed [bh, e, t]
__device__ __nv_bfloat16 g_Phi[67108864], g_Plo[67108864];       // softmax probs split
__device__ __nv_bfloat16 g_Ohi[16777216], g_Olo[16777216];       // [B*S, H*D] concat layout

// ---------------- helpers ----------------
__device__ __forceinline__ uint32_t smem_u32(const void* p) {
    uint32_t a;
    asm("{ .reg .u64 t; cvta.to.shared.u64 t, %1; cvt.u32.u64 %0, t; }" : "=r"(a) : "l"(p));
    return a;
}

__device__ __forceinline__ void split_store2(float a, float b,
                                             __nv_bfloat16* dhi, __nv_bfloat16* dlo) {
    __nv_bfloat16 h0 = __float2bfloat16_rn(a), h1 = __float2bfloat16_rn(b);
    __nv_bfloat16 l0 = __float2bfloat16_rn(a - __bfloat162float(h0));
    __nv_bfloat16 l1 = __float2bfloat16_rn(b - __bfloat162float(h1));
    *(uint32_t*)dhi = (uint32_t)__bfloat16_as_ushort(h0) | ((uint32_t)__bfloat16_as_ushort(h1) << 16);
    *(uint32_t*)dlo = (uint32_t)__bfloat16_as_ushort(l0) | ((uint32_t)__bfloat16_as_ushort(l1) << 16);
}

// ---------------------------------------------------------------------------
// Warp-MMA GEMM mainloop (legacy HMMA path — valid on compute_100 PTX).
// C[128,128] tile = sum over 3 bf16-split passes of A[128,K] * B[128,K]^T.
// Block: 256 threads = 8 warps arranged 2(M) x 4(N); warp tile 64x32;
// per-warp fragments: 4 Mfrag x 4 Nfrag of m16n8k16. BK=32, double-buffered
// cp.async pipeline. smem rows padded to 40 halves (conflict-free ldmatrix).
// acc[mf][nf][e]: e0,e1 = (row, col),(row, col+1); e2,e3 = row+8.
// ---------------------------------------------------------------------------
__device__ __forceinline__ void mma_gemm(
    const __nv_bfloat16* __restrict__ Ahi, const __nv_bfloat16* __restrict__ Alo,
    const __nv_bfloat16* __restrict__ Bhi, const __nv_bfloat16* __restrict__ Blo,
    int ldA, int ldB, int ksteps, float acc[4][4][4])
{
    __shared__ __nv_bfloat16 sA[2][128][40];
    __shared__ __nv_bfloat16 sB[2][128][40];

    int t = threadIdx.x;
    int lane = t & 31, wid = t >> 5;
    int wm = wid & 1, wn = wid >> 1;

    #pragma unroll
    for (int mf = 0; mf < 4; mf++)
        #pragma unroll
        for (int nf = 0; nf < 4; nf++)
            #pragma unroll
            for (int e = 0; e < 4; e++) acc[mf][nf][e] = 0.f;

    int total = 3 * ksteps;

    auto load_tile = [&](int c, int buf) {
        int pass = c / ksteps, kc = c - pass * ksteps;
        const __nv_bfloat16* Ap = (pass == 1) ? Alo : Ahi;
        const __nv_bfloat16* Bp = (pass == 2) ? Blo : Bhi;
        size_t kbase = (size_t)kc * 32;
        #pragma unroll
        for (int i = 0; i < 2; i++) {
            int idx = t + (i << 8);
            int row = idx >> 2, q = idx & 3;
            uint32_t sa = smem_u32(&sA[buf][row][q * 8]);
            const void* ga = Ap + (size_t)row * ldA + kbase + q * 8;
            asm volatile("cp.async.cg.shared.global [%0], [%1], 16;" :: "r"(sa), "l"(ga));
            uint32_t sb = smem_u32(&sB[buf][row][q * 8]);
            const void* gb = Bp + (size_t)row * ldB + kbase + q * 8;
            asm volatile("cp.async.cg.shared.global [%0], [%1], 16;" :: "r"(sb), "l"(gb));
        }
        asm volatile("cp.async.commit_group;");
    };

    load_tile(0, 0);

    for (int c = 0; c < total; c++) {
        if (c + 1 < total) {
            load_tile(c + 1, (c + 1) & 1);
            asm volatile("cp.async.wait_group 1;");
        } else {
            asm volatile("cp.async.wait_group 0;");
        }
        __syncthreads();

        int buf = c & 1;
        #pragma unroll
        for (int k16 = 0; k16 < 2; k16++) {
            uint32_t af[4][4];
            #pragma unroll
            for (int mf = 0; mf < 4; mf++) {
                int row = wm * 64 + mf * 16 + (lane & 15);
                int ko  = k16 * 16 + (lane >> 4) * 8;
                uint32_t addr = smem_u32(&sA[buf][row][ko]);
                asm volatile("ldmatrix.sync.aligned.m8n8.x4.shared.b16 {%0,%1,%2,%3}, [%4];"
                    : "=r"(af[mf][0]), "=r"(af[mf][1]), "=r"(af[mf][2]), "=r"(af[mf][3])
                    : "r"(addr));
            }
            uint32_t bfr[4][2];
            #pragma unroll
            for (int p = 0; p < 2; p++) {
                int nrow = wn * 32 + p * 16 + (lane & 7) + ((lane >> 4) << 3);
                int ko   = k16 * 16 + ((lane >> 3) & 1) * 8;
                uint32_t addr = smem_u32(&sB[buf][nrow][ko]);
                uint32_t r0, r1, r2, r3;
                asm volatile("ldmatrix.sync.aligned.m8n8.x4.shared.b16 {%0,%1,%2,%3}, [%4];"
                    : "=r"(r0), "=r"(r1), "=r"(r2), "=r"(r3) : "r"(addr));
                bfr[2*p][0] = r0; bfr[2*p][1] = r1;
                bfr[2*p+1][0] = r2; bfr[2*p+1][1] = r3;
            }
            #pragma unroll
            for (int mf = 0; mf < 4; mf++)
                #pragma unroll
                for (int nf = 0; nf < 4; nf++)
                    asm volatile(
                        "mma.sync.aligned.m16n8k16.row.col.f32.bf16.bf16.f32 "
                        "{%0,%1,%2,%3}, {%4,%5,%6,%7}, {%8,%9}, {%0,%1,%2,%3};"
                        : "+f"(acc[mf][nf][0]), "+f"(acc[mf][nf][1]),
                          "+f"(acc[mf][nf][2]), "+f"(acc[mf][nf][3])
                        : "r"(af[mf][0]), "r"(af[mf][1]), "r"(af[mf][2]), "r"(af[mf][3]),
                          "r"(bfr[nf][0]), "r"(bfr[nf][1]));
        }
        __syncthreads();
    }
}

// ---------------------------------------------------------------------------
// Kernel: split fp32 -> bf16 hi/lo
// ---------------------------------------------------------------------------
__global__ __launch_bounds__(256) void split_kernel(
    const float* __restrict__ src, __nv_bfloat16* __restrict__ hi,
    __nv_bfloat16* __restrict__ lo, int n4)
{
    int i = blockIdx.x * 256 + threadIdx.x;
    if (i >= n4) return;
    float4 v = *(const float4*)(src + 4 * (size_t)i);
    float a[4] = {v.x, v.y, v.z, v.w};
    uint32_t ph[2], pl[2];
    #pragma unroll
    for (int g = 0; g < 2; g++) {
        __nv_bfloat16 h0 = __float2bfloat16_rn(a[2*g]), h1 = __float2bfloat16_rn(a[2*g+1]);
        __nv_bfloat16 l0 = __float2bfloat16_rn(a[2*g] - __bfloat162float(h0));
        __nv_bfloat16 l1 = __float2bfloat16_rn(a[2*g+1] - __bfloat162float(h1));
        ph[g] = (uint32_t)__bfloat16_as_ushort(h0) | ((uint32_t)__bfloat16_as_ushort(h1) << 16);
        pl[g] = (uint32_t)__bfloat16_as_ushort(l0) | ((uint32_t)__bfloat16_as_ushort(l1) << 16);
    }
    *(uint2*)((char*)hi + 8 * (size_t)i) = make_uint2(ph[0], ph[1]);
    *(uint2*)((char*)lo + 8 * (size_t)i) = make_uint2(pl[0], pl[1]);
}

// ---------------------------------------------------------------------------
// Kernel: QKV projection.  grid (8, 2, 192): z = qkv*64 + b*8 + h
// ---------------------------------------------------------------------------
__global__ __launch_bounds__(256) void qkv_g(
    const float* __restrict__ bq, const float* __restrict__ bk, const float* __restrict__ bv)
{
    int z = blockIdx.z, qkv = z >> 6, bh = z & 63, b = bh >> 3, h = bh & 7;
    int m0 = blockIdx.x * 128, n0 = blockIdx.y * 128;

    const __nv_bfloat16* Whi = (qkv == 0) ? g_Wqhi : (qkv == 1) ? g_Wkhi : g_Wvhi;
    const __nv_bfloat16* Wlo = (qkv == 0) ? g_Wqlo : (qkv == 1) ? g_Wklo : g_Wvlo;
    const float* bias = ((qkv == 0) ? bq : (qkv == 1) ? bk : bv) + h * ND + n0;

    float acc[4][4][4];
    mma_gemm(g_Xhi + ((size_t)b * NS + m0) * ND, g_Xlo + ((size_t)b * NS + m0) * ND,
             Whi + (size_t)h * ND * ND + (size_t)n0 * ND,
             Wlo + (size_t)h * ND * ND + (size_t)n0 * ND,
             ND, ND, 8, acc);

    __nv_bfloat16* Ohi = (qkv == 0) ? g_Qhi : (qkv == 1) ? g_Khi : g_Vhi;
    __nv_bfloat16* Olo = (qkv == 0) ? g_Qlo : (qkv == 1) ? g_Klo : g_Vlo;

    int lane = threadIdx.x & 31, wid = threadIdx.x >> 5;
    int wm = wid & 1, wn = wid >> 1;
    #pragma unroll
    for (int mf = 0; mf < 4; mf++) {
        int r = m0 + wm * 64 + mf * 16 + (lane >> 2);
        #pragma unroll
        for (int nf = 0; nf < 4; nf++) {
            int cc = wn * 32 + nf * 8 + ((lane & 3) << 1);
            float2 bb = *(const float2*)(bias + cc);
            size_t base0 = ((size_t)bh * NS + r) * ND + n0 + cc;
            size_t base1 = base0 + 8 * ND;
            split_store2(acc[mf][nf][0] + bb.x, acc[mf][nf][1] + bb.y, Ohi + base0, Olo + base0);
            split_store2(acc[mf][nf][2] + bb.x, acc[mf][nf][3] + bb.y, Ohi + base1, Olo + base1);
        }
    }
}

// ---------------------------------------------------------------------------
// Kernel: V transpose [bh,t,e] -> [bh,e,t] (hi+lo). grid (32, 8, 64), block (32,8)
// ---------------------------------------------------------------------------
__global__ void vt_kernel()
{
    __shared__ __nv_bfloat16 th[32][33], tl[32][33];
    int bh = blockIdx.z, t0 = blockIdx.x * 32, e0 = blockIdx.y * 32;
    int tx = threadIdx.x, ty = threadIdx.y;
    #pragma unroll
    for (int j = 0; j < 4; j++) {
        int rr = ty + j * 8;
        size_t idx = ((size_t)bh * NS + t0 + rr) * ND + e0 + tx;
        th[rr][tx] = g_Vhi[idx];
        tl[rr][tx] = g_Vlo[idx];
    }
    __syncthreads();
    #pragma unroll
    for (int j = 0; j < 4; j++) {
        int er = ty + j * 8;
        size_t idx = ((size_t)bh * ND + e0 + er) * NS + t0 + tx;
        g_Vthi[idx] = th[tx][er];
        g_Vtlo[idx] = tl[tx][er];
    }
}

// ---------------------------------------------------------------------------
// Kernel: scores = QK^T / 16.  grid (8, 8, 64)
// ---------------------------------------------------------------------------
__global__ __launch_bounds__(256) void scores_g()
{
    int bh = blockIdx.z, m0 = blockIdx.x * 128, n0 = blockIdx.y * 128;
    float acc[4][4][4];
    mma_gemm(g_Qhi + ((size_t)bh * NS + m0) * ND, g_Qlo + ((size_t)bh * NS + m0) * ND,
             g_Khi + ((size_t)bh * NS + n0) * ND, g_Klo + ((size_t)bh * NS + n0) * ND,
             ND, ND, 8, acc);

    int lane = threadIdx.x & 31, wid = threadIdx.x >> 5;
    int wm = wid & 1, wn = wid >> 1;
    #pragma unroll
    for (int mf = 0; mf < 4; mf++) {
        int r = m0 + wm * 64 + mf * 16 + (lane >> 2);
        #pragma unroll
        for (int nf = 0; nf < 4; nf++) {
            int cc = n0 + wn * 32 + nf * 8 + ((lane & 3) << 1);
            float* d0 = g_P + ((size_t)bh * NS + r) * NS + cc;
            *(float2*)d0 = make_float2(acc[mf][nf][0] * 0.0625f, acc[mf][nf][1] * 0.0625f);
            *(float2*)(d0 + 8 * NS) = make_float2(acc[mf][nf][2] * 0.0625f, acc[mf][nf][3] * 0.0625f);
        }
    }
}

// ---------------------------------------------------------------------------
// Kernel: softmax over keys + bf16 hi/lo split.  grid 65536, block 256
// ---------------------------------------------------------------------------
__global__ __launch_bounds__(256) void softmax_kernel()
{
    size_t rowoff = (size_t)blockIdx.x * NS;
    const float* p = g_P + rowoff;
    int t = threadIdx.x;
    float4 v = *(const float4*)(p + (t << 2));
    __shared__ float sm[8], ss[8];

    float m = fmaxf(fmaxf(v.x, v.y), fmaxf(v.z, v.w));
    #pragma unroll
    for (int o = 16; o > 0; o >>= 1) m = fmaxf(m, __shfl_xor_sync(0xffffffffu, m, o));
    if ((t & 31) == 0) sm[t >> 5] = m;
    __syncthreads();
    if (t < 32) {
        float mm = (t < 8) ? sm[t] : -3.0e38f;
        #pragma unroll
        for (int o = 4; o > 0; o >>= 1) mm = fmaxf(mm, __shfl_xor_sync(0xffffffffu, mm, o));
        if (t == 0) sm[0] = mm;
    }
    __syncthreads();
    m = sm[0];
    v.x = __expf(v.x - m); v.y = __expf(v.y - m);
    v.z = __expf(v.z - m); v.w = __expf(v.w - m);
    float s = v.x + v.y + v.z + v.w;
    #pragma unroll
    for (int o = 16; o > 0; o >>= 1) s += __shfl_xor_sync(0xffffffffu, s, o);
    if ((t & 31) == 0) ss[t >> 5] = s;
    __syncthreads();
    if (t < 32) {
        float sv = (t < 8) ? ss[t] : 0.f;
        #pragma unroll
        for (int o = 4; o > 0; o >>= 1) sv += __shfl_xor_sync(0xffffffffu, sv, o);
        if (t == 0) ss[0] = sv;
    }
    __syncthreads();
    float inv = 1.0f / ss[0];
    float a[4] = {v.x * inv, v.y * inv, v.z * inv, v.w * inv};

    uint32_t ph[2], pl[2];
    #pragma unroll
    for (int g = 0; g < 2; g++) {
        __nv_bfloat16 h0 = __float2bfloat16_rn(a[2*g]), h1 = __float2bfloat16_rn(a[2*g+1]);
        __nv_bfloat16 l0 = __float2bfloat16_rn(a[2*g] - __bfloat162float(h0));
        __nv_bfloat16 l1 = __float2bfloat16_rn(a[2*g+1] - __bfloat162float(h1));
        ph[g] = (uint32_t)__bfloat16_as_ushort(h0) | ((uint32_t)__bfloat16_as_ushort(h1) << 16);
        pl[g] = (uint32_t)__bfloat16_as_ushort(l0) | ((uint32_t)__bfloat16_as_ushort(l1) << 16);
    }
    *(uint2*)((char*)g_Phi + 2 * (rowoff + (t << 2))) = make_uint2(ph[0], ph[1]);
    *(uint2*)((char*)g_Plo + 2 * (rowoff + (t << 2))) = make_uint2(pl[0], pl[1]);
}

// ---------------------------------------------------------------------------
// Kernel: O = P @ V (B = V^T).  grid (8, 2, 64) -> concat layout
// ---------------------------------------------------------------------------
__global__ __launch_bounds__(256) void pv_g()
{
    int bh = blockIdx.z, b = bh >> 3, h = bh & 7;
    int m0 = blockIdx.x * 128, n0 = blockIdx.y * 128;
    float acc[4][4][4];
    mma_gemm(g_Phi + ((size_t)bh * NS + m0) * NS, g_Plo + ((size_t)bh * NS + m0) * NS,
             g_Vthi + (size_t)bh * ND * NS + (size_t)n0 * NS,
             g_Vtlo + (size_t)bh * ND * NS + (size_t)n0 * NS,
             NS, NS, 32, acc);

    int lane = threadIdx.x & 31, wid = threadIdx.x >> 5;
    int wm = wid & 1, wn = wid >> 1;
    #pragma unroll
    for (int mf = 0; mf < 4; mf++) {
        int r = m0 + wm * 64 + mf * 16 + (lane >> 2);
        #pragma unroll
        for (int nf = 0; nf < 4; nf++) {
            int cc = n0 + wn * 32 + nf * 8 + ((lane & 3) << 1);
            size_t base0 = ((size_t)(b * NS + r)) * HD + h * ND + cc;
            size_t base1 = base0 + 8 * HD;
            split_store2(acc[mf][nf][0], acc[mf][nf][1], g_Ohi + base0, g_Olo + base0);
            split_store2(acc[mf][nf][2], acc[mf][nf][3], g_Ohi + base1, g_Olo + base1);
        }
    }
}

// ---------------------------------------------------------------------------
// Kernel: out = concat(O) @ Wp^T.  grid (64, 2, 1)
// ---------------------------------------------------------------------------
__global__ __launch_bounds__(256) void proj_g(float* __restrict__ out)
{
    int m0 = blockIdx.x * 128, n0 = blockIdx.y * 128;
    float acc[4][4][4];
    mma_gemm(g_Ohi + (size_t)m0 * HD, g_Olo + (size_t)m0 * HD,
             g_Wphi + (size_t)n0 * HD, g_Wplo + (size_t)n0 * HD,
             HD, HD, 64, acc);

    int lane = threadIdx.x & 31, wid = threadIdx.x >> 5;
    int wm = wid & 1, wn = wid >> 1;
    #pragma unroll
    for (int mf = 0; mf < 4; mf++) {
        int r = m0 + wm * 64 + mf * 16 + (lane >> 2);
        #pragma unroll
        for (int nf = 0; nf < 4; nf++) {
            int cc = n0 + wn * 32 + nf * 8 + ((lane & 3) << 1);
            float* d0 = out + (size_t)r * ND + cc;
            *(float2*)d0 = make_float2(acc[mf][nf][0], acc[mf][nf][1]);
            *(float2*)(d0 + 8 * ND) = make_float2(acc[mf][nf][2], acc[mf][nf][3]);
        }
    }
}

// ---------------------------------------------------------------------------
extern "C" void kernel_launch(void* const* d_in, const int* in_sizes, int n_in,
                              void* d_out, int out_size)
{
    const float* x  = (const float*)d_in[0];
    const float* Wq = (const float*)d_in[1];
    const float* Wk = (const float*)d_in[2];
    const float* Wv = (const float*)d_in[3];
    const float* bq = (const float*)d_in[4];
    const float* bk = (const float*)d_in[5];
    const float* bv = (const float*)d_in[6];
    const float* Wp = (const float*)d_in[7];
    float* out = (float*)d_out;

    __nv_bfloat16 *Xhi, *Xlo, *Wqhi, *Wqlo, *Wkhi, *Wklo, *Wvhi, *Wvlo, *Wphi, *Wplo;
    cudaGetSymbolAddress((void**)&Xhi,  g_Xhi);  cudaGetSymbolAddress((void**)&Xlo,  g_Xlo);
    cudaGetSymbolAddress((void**)&Wqhi, g_Wqhi); cudaGetSymbolAddress((void**)&Wqlo, g_Wqlo);
    cudaGetSymbolAddress((void**)&Wkhi, g_Wkhi); cudaGetSymbolAddress((void**)&Wklo, g_Wklo);
    cudaGetSymbolAddress((void**)&Wvhi, g_Wvhi); cudaGetSymbolAddress((void**)&Wvlo, g_Wvlo);
    cudaGetSymbolAddress((void**)&Wphi, g_Wphi); cudaGetSymbolAddress((void**)&Wplo, g_Wplo);

    split_kernel<<<2048, 256>>>(x,  Xhi,  Xlo,  524288);   // 8*1024*256 / 4
    split_kernel<<<512,  256>>>(Wq, Wqhi, Wqlo, 131072);
    split_kernel<<<512,  256>>>(Wk, Wkhi, Wklo, 131072);
    split_kernel<<<512,  256>>>(Wv, Wvhi, Wvlo, 131072);
    split_kernel<<<512,  256>>>(Wp, Wphi, Wplo, 131072);

    dim3 gq(8, 2, 192);
    qkv_g<<<gq, 256>>>(bq, bk, bv);

    dim3 gt(32, 8, 64);
    vt_kernel<<<gt, dim3(32, 8)>>>();

    dim3 gs(8, 8, 64);
    scores_g<<<gs, 256>>>();

    softmax_kernel<<<65536, 256>>>();

    dim3 gp(8, 2, 64);
    pv_g<<<gp, 256>>>();

    dim3 go(64, 2, 1);
    proj_g<<<go, 256>>>(out);
}